// round 12
// baseline (speedup 1.0000x reference)
#include <cuda_runtime.h>
#include <cuda_bf16.h>
#include <cstdint>

#define NCTA 128
#define NTHR 256
#define B_   128
#define T_   800
#define H_   256
#define U_   64
#define KMIX 10
#define GMIX 20
#define A_   64
#define TB_  (T_*B_)
#define RPC  64          // rows per CTA
#define UPC  4           // units per CTA (16 gate cols)

// smem layout (float offsets)
#define OFF_W1   0       // [5168]  LSTM1 weights (KTOT=323, 16 cols)
#define OFF_W2   5168    // [9264]  LSTM2 (KTOT=579)
#define OFF_W3   14432   // [9264]  LSTM3
#define OFF_B    23696   // [48]    biases (16 per layer)
#define OFF_BW   23744   // [64*68] w buffer
#define OFF_H0   28096   // [64*132]
#define OFF_H1   36544   // [64*132]
#define OFF_H2   44992   // [64*132]
#define OFF_G    53440   // [64*16] gates
#define OFF_C    54464   // [3*256] cell states
#define OFF_HR   55232   // [256]
#define OFF_WIN  55488   // [32]
#define OFF_KAP  55520   // [16]
#define OFF_PHI  55536   // [64]
#define OFF_CIDX 55600   // [64] ints
#define SMEM_FLOATS 55664
#define SMEM_BYTES (SMEM_FLOATS*4)   // 222656 B < 227KB opt-in

// per-layer weight sub-layout (pair-interleaved, 16 cols):
//   [0,48):    x rows, k*16 + j
//   [48,1072): w segment, pair p: 48 + p*32 + j*2 + parity
//   [1072 + c*2048, ...): h chunk c (64 pairs x 32)

// ------------------------- persistent device state ---------------------------
__device__ __align__(16) float g_h1[2][B_*H_];
__device__ __align__(16) float g_h2[2][B_*H_];
__device__ __align__(16) float g_h3[2][B_*H_];
__device__ __align__(16) float g_w[B_*A_];
__device__ __align__(16) float g_hist[(size_t)T_*B_*H_];
__device__ unsigned g_arrive;
__device__ volatile unsigned g_epoch;

__device__ __forceinline__ float sigmf(float x) { return 1.0f/(1.0f+expf(-x)); }

// ------------------------- f32x2 helpers --------------------------------------
__device__ __forceinline__ void fma2(unsigned long long& acc,
                                     unsigned long long a, unsigned long long b) {
  asm("fma.rn.f32x2 %0, %1, %2, %3;" : "=l"(acc) : "l"(a), "l"(b), "l"(acc));
}
__device__ __forceinline__ unsigned long long packf2(float lo, float hi) {
  unsigned long long r;
  asm("mov.b64 %0, {%1, %2};" : "=l"(r) : "f"(lo), "f"(hi));
  return r;
}
__device__ __forceinline__ float hsumf2(unsigned long long v) {
  float lo, hi;
  asm("mov.b64 {%0, %1}, %2;" : "=f"(lo), "=f"(hi) : "l"(v));
  return lo + hi;
}

// ------------------------- cp.async helpers ----------------------------------
__device__ __forceinline__ unsigned smem_u32(const void* p) {
  return (unsigned)__cvta_generic_to_shared(p);
}
__device__ __forceinline__ void cpa16(unsigned dst, const float* src) {
  asm volatile("cp.async.cg.shared.global [%0], [%1], 16;\n" :: "r"(dst), "l"(src));
}
#define CP_COMMIT  asm volatile("cp.async.commit_group;\n")
#define CP_WAIT(n) asm volatile("cp.async.wait_group %0;\n" :: "n"(n))

// ------------------------- grid barrier (epoch counting) ---------------------
__device__ __forceinline__ void gbar(unsigned e) {
  __syncthreads();
  if (threadIdx.x == 0) {
    __threadfence();
    unsigned v = atomicAdd(&g_arrive, 1u);
    if (v == e*(unsigned)NCTA - 1u) {
      atomicExch((unsigned*)&g_epoch, e);
    } else {
      while (g_epoch < e) { __nanosleep(32); }
    }
    __threadfence();
  }
  __syncthreads();
}

// ------------------------- staging -------------------------------------------
// stage one 128-wide K chunk of rows [0,64) of (src already offset by b0*H)
__device__ __forceinline__ void stage_h(float* buf, const float* src, int k0, int tid) {
  #pragma unroll
  for (int n = 0; n < 8; ++n) {
    int i = tid + n*NTHR;
    int r = i >> 5, kq = i & 31;
    cpa16(smem_u32(buf + r*132 + kq*4), src + r*256 + k0 + kq*4);
  }
}
// stage w rows [b0, b0+64) into bufW[64][68]
__device__ __forceinline__ void stage_w(float* buf, int b0, int tid) {
  #pragma unroll
  for (int n = 0; n < 4; ++n) {
    int i = tid + n*NTHR;
    int r = i >> 4, kq = i & 15;
    cpa16(smem_u32(buf + r*68 + kq*4), g_w + (b0 + r)*64 + kq*4);
  }
}

// ------------------------- paired FMA chunk (NP k-pairs, stride-32 rows) ------
template<int NP>
__device__ __forceinline__ void chunk_fma2(
    unsigned long long& q0, unsigned long long& q1,
    unsigned long long& q2, unsigned long long& q3,
    const float* __restrict__ ar,   // act row ptr (pairs contiguous)
    const float* __restrict__ wk)   // pair-row base + cg*8
{
  #pragma unroll 4
  for (int p = 0; p < NP; ++p) {
    unsigned long long av = *(const unsigned long long*)(ar + 2*p);
    ulonglong2 w01 = *(const ulonglong2*)(wk + p*32);
    ulonglong2 w23 = *(const ulonglong2*)(wk + p*32 + 4);
    fma2(q0, av, w01.x); fma2(q1, av, w01.y);
    fma2(q2, av, w23.x); fma2(q3, av, w23.y);
  }
}

// ------------------------- LSTM phase ----------------------------------------
// CTA owns units [ucol0, ucol0+4) x rows [b0, b0+64). Virtual input:
// [x(3) | w(64) | hA(256) | hB(256 iff HASB)]. Col j = gate*4 + du.
// Thread: row = tid>>2, cg = tid&3 (owns gate cg, 4 units).
template<bool HASB, bool STAGEW>
__device__ __forceinline__ void lstm_phase(
    float* __restrict__ sm,
    const float* __restrict__ wsmL, const float* __restrict__ bsmL,
    float* __restrict__ csmL,
    int t, int b0, int ucol0, int tid,
    const float* __restrict__ x,
    const float* __restrict__ hA, const float* __restrict__ hB,
    float* __restrict__ hout, float* __restrict__ histp)
{
  float* bufW = sm + OFF_BW;
  float* h0   = sm + OFF_H0;
  float* h1b  = sm + OFF_H1;
  float* h2b  = sm + OFF_H2;
  float* gsm  = sm + OFF_G;
  const int row = tid >> 2, cg = tid & 3;
  const float* hAo = hA + b0*H_;

  // issue all stages up-front (deep pipeline)
  if (STAGEW) { stage_w(bufW, b0, tid); CP_COMMIT; }   // Gw
  stage_h(h0,  hAo, 0,   tid); CP_COMMIT;              // Ga
  stage_h(h1b, hAo, 128, tid); CP_COMMIT;              // Gb
  const float* hBo = HASB ? hB + b0*H_ : (const float*)0;
  if (HASB) { stage_h(h2b, hBo, 0, tid); CP_COMMIT; }  // Gc

  // x part (k = 0..2)
  unsigned long long q0, q1, q2, q3;
  {
    const float* xr = x + ((b0 + row)*T_ + t)*3;
    float xv0=__ldg(xr), xv1=__ldg(xr+1), xv2=__ldg(xr+2);
    const float* wk = wsmL + cg*4;
    float4 w0=*(const float4*)(wk), w1=*(const float4*)(wk+16), w2=*(const float4*)(wk+32);
    float a0 = xv0*w0.x + xv1*w1.x + xv2*w2.x;
    float a1 = xv0*w0.y + xv1*w1.y + xv2*w2.y;
    float a2 = xv0*w0.z + xv1*w1.z + xv2*w2.z;
    float a3 = xv0*w0.w + xv1*w1.w + xv2*w2.w;
    q0 = packf2(a0, 0.f); q1 = packf2(a1, 0.f);
    q2 = packf2(a2, 0.f); q3 = packf2(a3, 0.f);
  }
  if (STAGEW) { CP_WAIT(3); __syncthreads(); }   // Gw done (only in C: 3 pending)
  // w segment (k = 3..66), bufW valid (staged now or left from prior phase)
  chunk_fma2<32>(q0,q1,q2,q3, bufW + row*68, wsmL + 48 + cg*8);

  CP_WAIT(STAGEW ? 2 : (HASB ? 2 : 1)); __syncthreads();   // Ga done
  chunk_fma2<64>(q0,q1,q2,q3, h0 + row*132, wsmL + 1072 + cg*8);
  if (HASB) {
    __syncthreads();                                 // all done reading h0
    stage_h(h0, hBo, 128, tid); CP_COMMIT;           // Gd into h0
    CP_WAIT(2); __syncthreads();                     // Gb done
    chunk_fma2<64>(q0,q1,q2,q3, h1b + row*132, wsmL + 1072 + 2048 + cg*8);
    CP_WAIT(1); __syncthreads();                     // Gc done
    chunk_fma2<64>(q0,q1,q2,q3, h2b + row*132, wsmL + 1072 + 4096 + cg*8);
    CP_WAIT(0); __syncthreads();                     // Gd done
    chunk_fma2<64>(q0,q1,q2,q3, h0 + row*132, wsmL + 1072 + 6144 + cg*8);
  } else {
    CP_WAIT(0); __syncthreads();                     // Gb done
    chunk_fma2<64>(q0,q1,q2,q3, h1b + row*132, wsmL + 1072 + 2048 + cg*8);
  }
  // bias + gate stash: cols j = cg*4 .. cg*4+3
  {
    float4 bv = *(const float4*)(bsmL + cg*4);
    float4 g;
    g.x = hsumf2(q0) + bv.x; g.y = hsumf2(q1) + bv.y;
    g.z = hsumf2(q2) + bv.z; g.w = hsumf2(q3) + bv.w;
    *(float4*)(gsm + row*16 + cg*4) = g;
  }
  __syncthreads();
  // cell update: thread = (row r, unit du); col j = gate*4 + du
  {
    const int r = tid >> 2, du = tid & 3;
    const float* gr = gsm + r*16;
    float ii = sigmf(gr[du]);
    float ff = sigmf(gr[4 + du]);
    float gg = tanhf(gr[8 + du]);
    float oo = sigmf(gr[12 + du]);
    float cv = ff*csmL[tid] + ii*gg;
    csmL[tid] = cv;
    float hv = oo*tanhf(cv);
    int gi = (b0 + r)*H_ + ucol0 + du;
    __stcg(&hout[gi], hv);
    if (histp) histp[gi] = hv;
  }
  __syncthreads();
}

// ------------------------- weight preload (pair-interleaved, 16 cols) ---------
__device__ __forceinline__ void preload_w(
    float* dst, const float* __restrict__ Wih, const float* __restrict__ Whh,
    int KIN, int KTOT, int ucol0, int tid)
{
  for (int i = tid; i < KTOT*16; i += NTHR) {
    int k = i >> 4, j = i & 15, gate = j >> 2, du = j & 3;
    int col = gate*256 + ucol0 + du;
    float v = (k < KIN) ? __ldg(&Wih[k*1024 + col]) : __ldg(&Whh[(k-KIN)*1024 + col]);
    int idx;
    if (k < 3) {
      idx = k*16 + j;
    } else if (k < 67) {
      int kk = k - 3;
      idx = 48 + (kk >> 1)*32 + j*2 + (kk & 1);
    } else {
      int kk = k - 67;
      int c = kk >> 7, r = kk & 127;
      idx = 1072 + c*2048 + (r >> 1)*32 + j*2 + (r & 1);
    }
    dst[idx] = v;
  }
}

// ------------------------- reset (per launch) --------------------------------
__global__ void reset_kernel() { g_arrive = 0u; g_epoch = 0u; }

// ------------------------- main persistent kernel ----------------------------
__global__ void __launch_bounds__(NTHR, 1) main_kernel(
    const float* __restrict__ x,  const int* __restrict__ cc,
    const float* __restrict__ Wih1, const float* __restrict__ Whh1,
    const float* __restrict__ bih1, const float* __restrict__ bhh1,
    const float* __restrict__ Wih2, const float* __restrict__ Whh2,
    const float* __restrict__ bih2, const float* __restrict__ bhh2,
    const float* __restrict__ Wih3, const float* __restrict__ Whh3,
    const float* __restrict__ bih3, const float* __restrict__ bhh3,
    const float* __restrict__ Ww,   const float* __restrict__ bw)
{
  extern __shared__ float sm[];
  float* wsm1 = sm + OFF_W1;
  float* wsm2 = sm + OFF_W2;
  float* wsm3 = sm + OFF_W3;
  float* bsm  = sm + OFF_B;
  float* bufW = sm + OFF_BW;
  float* csm  = sm + OFF_C;      // [3][256]
  float* h1row= sm + OFF_HR;
  float* win  = sm + OFF_WIN;
  float* kap  = sm + OFF_KAP;
  float* Phi  = sm + OFF_PHI;
  int*   cidx = (int*)(sm + OFF_CIDX);

  const int tid = threadIdx.x;
  const int cta = blockIdx.x;
  const int b0    = (cta >> 6) * RPC;     // row tile base
  const int ucol0 = (cta & 63) * UPC;     // unit tile base
  const int brow = cta;                   // window-phase batch row

  // ---- one-time preload: all weights for this CTA's 16 gate-columns ----
  preload_w(wsm1, Wih1, Whh1, 67,  323, ucol0, tid);
  preload_w(wsm2, Wih2, Whh2, 323, 579, ucol0, tid);
  preload_w(wsm3, Wih3, Whh3, 323, 579, ucol0, tid);
  if (tid < 16) {
    int gate = tid >> 2, du = tid & 3, col = gate*256 + ucol0 + du;
    bsm[tid]      = __ldg(&bih1[col]) + __ldg(&bhh1[col]);
    bsm[16 + tid] = __ldg(&bih2[col]) + __ldg(&bhh2[col]);
    bsm[32 + tid] = __ldg(&bih3[col]) + __ldg(&bhh3[col]);
  }
  { csm[tid]=0.f; csm[256+tid]=0.f; csm[512+tid]=0.f; }
  if (tid < 16) kap[tid] = 0.f;
  if (tid < 64) cidx[tid] = __ldg(&cc[brow*U_ + tid]);
  // seed bufW with initial w = 1 (phase A at t=0 reuses it without staging)
  #pragma unroll
  for (int n = 0; n < 16; ++n) {
    int i = tid + n*NTHR;
    bufW[(i >> 6)*68 + (i & 63)] = 1.0f;
  }
  // zero h state, w = 1 (reference carry0)
  __stcg(&g_h1[0][brow*H_ + tid], 0.f);
  __stcg(&g_h2[0][brow*H_ + tid], 0.f);
  __stcg(&g_h3[0][brow*H_ + tid], 0.f);
  if (tid < 64) __stcg(&g_w[brow*A_ + tid], 1.0f);
  __syncthreads();

  unsigned ep = 1;
  gbar(ep++);

  for (int t = 0; t < T_; ++t) {
    const int p = t & 1;

    // ---- phase A: LSTM1  (x | w(t-1) from bufW | h1_rec) ----
    lstm_phase<false,false>(sm, wsm1, bsm, csm,
                            t, b0, ucol0, tid, x, g_h1[p], (const float*)0,
                            g_h1[1-p], (float*)0);
    gbar(ep++);

    // ---- phase B: attention window (CTA brow handles row brow) ----
    {
      const float* h1g = g_h1[1-p] + brow*H_;
      h1row[tid] = __ldcg(&h1g[tid]);
      __syncthreads();
      int j = tid >> 3, l = tid & 7;
      int jc = (j < 30) ? j : 0;
      float s = 0.f;
      for (int k = l; k < 256; k += 8) s = fmaf(h1row[k], __ldg(&Ww[k*30 + jc]), s);
      s += __shfl_xor_sync(0xffffffffu, s, 4);
      s += __shfl_xor_sync(0xffffffffu, s, 2);
      s += __shfl_xor_sync(0xffffffffu, s, 1);
      if (l == 0 && j < 30) win[j] = expf(s + __ldg(&bw[j]));
      __syncthreads();
      if (tid < KMIX) kap[tid] += 0.1f * win[20 + tid];
      __syncthreads();
      if (tid < U_) {
        float u = (float)tid;
        float ph = 0.f;
        #pragma unroll
        for (int k = 0; k < KMIX; ++k) {
          float d = kap[k] - u;
          ph += win[k] * expf(-win[10 + k] * d * d);
        }
        Phi[tid] = ph;
      }
      __syncthreads();
      if (tid < A_) {
        float s2 = 0.f;
        #pragma unroll 4
        for (int u = 0; u < U_; ++u)
          if (cidx[u] == tid) s2 += Phi[u];
        __stcg(&g_w[brow*A_ + tid], s2);
      }
    }
    gbar(ep++);

    // ---- phase C: LSTM2  (x | w_new staged | h1_new | h2_rec) ----
    lstm_phase<true,true>(sm, wsm2, bsm + 16, csm + 256,
                          t, b0, ucol0, tid, x, g_h1[1-p], g_h2[p],
                          g_h2[1-p], (float*)0);
    gbar(ep++);

    // ---- phase D: LSTM3  (x | w_new from bufW | h2_new | h3_rec), + history ----
    lstm_phase<true,false>(sm, wsm3, bsm + 32, csm + 512,
                           t, b0, ucol0, tid, x, g_h2[1-p], g_h3[p],
                           g_h3[1-p], &g_hist[(size_t)t * B_ * H_]);
    // no barrier needed: D(t) overlaps only A(t+1), disjoint buffers; bufW
    // holds w(t) which is exactly what A(t+1) must consume.
  }
}

// ------------------------- MDN heads -----------------------------------------
#define PHEAD 8
__global__ void __launch_bounds__(128) heads_kernel(
    const float* __restrict__ We,   const float* __restrict__ be,
    const float* __restrict__ Wpi,  const float* __restrict__ bpi,
    const float* __restrict__ Wmu1, const float* __restrict__ bmu1,
    const float* __restrict__ Wmu2, const float* __restrict__ bmu2,
    const float* __restrict__ Ws1,  const float* __restrict__ bs1,
    const float* __restrict__ Ws2,  const float* __restrict__ bs2,
    const float* __restrict__ Wrho, const float* __restrict__ brho,
    float* __restrict__ out)
{
  __shared__ float hs[PHEAD*H_];
  __shared__ float raw[PHEAD][128];
  __shared__ float stat[PHEAD][2];
  const int p0  = blockIdx.x * PHEAD;
  const int tid = threadIdx.x;

  for (int i = tid; i < PHEAD*H_; i += 128)
    hs[i] = g_hist[(size_t)p0*H_ + i];
  __syncthreads();

  const int j = tid;
  if (j < 121) {
    const float* W; int stride, cs; float bias;
    if (j == 0)      { W = We;   stride = 1;  cs = 0;     bias = __ldg(&be[0]);    }
    else if (j < 21) { W = Wpi;  stride = 20; cs = j-1;   bias = __ldg(&bpi[cs]);  }
    else if (j < 41) { W = Wmu1; stride = 20; cs = j-21;  bias = __ldg(&bmu1[cs]); }
    else if (j < 61) { W = Wmu2; stride = 20; cs = j-41;  bias = __ldg(&bmu2[cs]); }
    else if (j < 81) { W = Ws1;  stride = 20; cs = j-61;  bias = __ldg(&bs1[cs]);  }
    else if (j < 101){ W = Ws2;  stride = 20; cs = j-81;  bias = __ldg(&bs2[cs]);  }
    else             { W = Wrho; stride = 20; cs = j-101; bias = __ldg(&brho[cs]); }
    float acc[PHEAD];
    #pragma unroll
    for (int r = 0; r < PHEAD; ++r) acc[r] = 0.f;
    #pragma unroll 4
    for (int k = 0; k < H_; ++k) {
      float wv = __ldg(&W[k*stride + cs]);
      #pragma unroll
      for (int r = 0; r < PHEAD; ++r) acc[r] = fmaf(hs[r*H_ + k], wv, acc[r]);
    }
    #pragma unroll
    for (int r = 0; r < PHEAD; ++r) raw[r][j] = acc[r] + bias;
  }
  __syncthreads();

  if (tid < PHEAD) {
    float m = -1e30f;
    for (int g = 1; g < 21; ++g) m = fmaxf(m, raw[tid][g]);
    float s = 0.f;
    for (int g = 1; g < 21; ++g) s += expf(raw[tid][g] - m);
    stat[tid][0] = m; stat[tid][1] = s;
  }
  __syncthreads();

  if (j < 121) {
    const int blk = (j == 0) ? -1 : (j-1)/20;
    const int g   = (j == 0) ? 0  : (j-1)%20;
    #pragma unroll
    for (int r = 0; r < PHEAD; ++r) {
      size_t p = (size_t)(p0 + r);
      float v = raw[r][j];
      if (j == 0) {
        out[p] = 1.0f / (1.0f + expf(v));
      } else {
        float o;
        if      (blk == 0) o = expf(v - stat[r][0]) / stat[r][1];
        else if (blk <= 2) o = v;
        else if (blk <= 4) o = expf(v);
        else               o = tanhf(v);
        out[(size_t)TB_ + (size_t)blk * (TB_*(size_t)GMIX) + p*GMIX + g] = o;
      }
    }
  }
}

// ------------------------- launch --------------------------------------------
extern "C" void kernel_launch(void* const* d_in, const int* in_sizes, int n_in,
                              void* d_out, int out_size) {
  const float* x    = (const float*)d_in[0];
  const int*   cc   = (const int*)  d_in[1];
  const float* Wih1 = (const float*)d_in[2];
  const float* Whh1 = (const float*)d_in[3];
  const float* bih1 = (const float*)d_in[4];
  const float* bhh1 = (const float*)d_in[5];
  const float* Wih2 = (const float*)d_in[6];
  const float* Whh2 = (const float*)d_in[7];
  const float* bih2 = (const float*)d_in[8];
  const float* bhh2 = (const float*)d_in[9];
  const float* Wih3 = (const float*)d_in[10];
  const float* Whh3 = (const float*)d_in[11];
  const float* bih3 = (const float*)d_in[12];
  const float* bhh3 = (const float*)d_in[13];
  const float* Ww   = (const float*)d_in[14];
  const float* bw   = (const float*)d_in[15];
  const float* We   = (const float*)d_in[16];
  const float* be   = (const float*)d_in[17];
  const float* Wpi  = (const float*)d_in[18];
  const float* bpi  = (const float*)d_in[19];
  const float* Wmu1 = (const float*)d_in[20];
  const float* bmu1 = (const float*)d_in[21];
  const float* Wmu2 = (const float*)d_in[22];
  const float* bmu2 = (const float*)d_in[23];
  const float* Ws1  = (const float*)d_in[24];
  const float* bs1  = (const float*)d_in[25];
  const float* Ws2  = (const float*)d_in[26];
  const float* bs2  = (const float*)d_in[27];
  const float* Wrho = (const float*)d_in[28];
  const float* brho = (const float*)d_in[29];
  float* out = (float*)d_out;

  cudaFuncSetAttribute(main_kernel, cudaFuncAttributeMaxDynamicSharedMemorySize, SMEM_BYTES);

  reset_kernel<<<1, 1>>>();
  main_kernel<<<NCTA, NTHR, SMEM_BYTES>>>(
      x, cc, Wih1, Whh1, bih1, bhh1, Wih2, Whh2, bih2, bhh2,
      Wih3, Whh3, bih3, bhh3, Ww, bw);
  heads_kernel<<<TB_/PHEAD, 128>>>(
      We, be, Wpi, bpi, Wmu1, bmu1, Wmu2, bmu2,
      Ws1, bs1, Ws2, bs2, Wrho, brho, out);
}